// round 14
// baseline (speedup 1.0000x reference)
#include <cuda_runtime.h>
#include <cuda_bf16.h>
#include <stdint.h>
#include <math.h>

// ---------------- problem constants ----------------
#define BB 4
#define HH 256
#define WW 256
#define CC 32
#define NPIX (HH*WW)            // 65536
#define IMG_ELEMS (BB*NPIX*CC)  // 8388608

typedef unsigned long long ull;

// ---------------- device scratch ----------------
__device__ float g_part[BB*256*1056];
__device__ float g_cov[BB*1056];
__device__ float g_cmask[BB*CC];
__device__ float g_smask[BB*NPIX];
__device__ float g_kcomb[49*32];
__device__ float g_outn[IMG_ELEMS];
__device__ __nv_bfloat16 g_vg_hi[IMG_ELEMS], g_vg_lo[IMG_ELEMS];
__device__ __nv_bfloat16 g_vs_hi[IMG_ELEMS], g_vs_lo[IMG_ELEMS];
__device__ __nv_bfloat16 g_tp_hi[IMG_ELEMS], g_tp_lo[IMG_ELEMS];
// padded bf16 weight tiles for mma convs: [conv 3][pass 2][dh 3][o 32][k 104]
#define WB_ROWS (6*32)
#define WB_STR  104
__device__ __nv_bfloat16 g_Wb[3*WB_ROWS*WB_STR];
// per-batch split M tiles: [b][pass 2][o 32][k 40]
#define MB_ELEM 2560
__device__ __nv_bfloat16 g_Mbt[BB*MB_ELEM];

__device__ __forceinline__ float gelu_exact(float x) {
    return 0.5f * x * (1.0f + erff(x * 0.70710678118654752f));
}
__device__ __forceinline__ float sigmoidf_(float x) {
    return 1.0f / (1.0f + expf(-x));
}

// ---------------- packed f32x2 helpers ----------------
__device__ __forceinline__ void fma2(ull& c, ull a, ull b) {
    asm("fma.rn.f32x2 %0, %1, %2, %0;" : "+l"(c) : "l"(a), "l"(b));
}
__device__ __forceinline__ ull pk2(float x) {
    ull r; asm("mov.b64 %0, {%1, %1};" : "=l"(r) : "f"(x)); return r;
}
__device__ __forceinline__ float2 upk(ull v) {
    float2 f; asm("mov.b64 {%0, %1}, %2;" : "=f"(f.x), "=f"(f.y) : "l"(v)); return f;
}
__device__ __forceinline__ float hadd2(ull v) {
    float2 f = upk(v); return f.x + f.y;
}
__device__ __forceinline__ uint32_t pkbf(float a, float b) {
    __nv_bfloat16 h0 = __float2bfloat16(a), h1 = __float2bfloat16(b);
    return (uint32_t)__bfloat16_as_ushort(h1) << 16 | __bfloat16_as_ushort(h0);
}
__device__ __forceinline__ uint32_t smem_to_u32(const void* p) {
    uint32_t a; asm("{ .reg .u64 t; cvta.to.shared.u64 t, %1; cvt.u32.u64 %0, t; }" : "=r"(a) : "l"(p)); return a;
}
__device__ __forceinline__ void mma_bf16(float (&d)[4], uint32_t a0, uint32_t a1,
                                         uint32_t a2, uint32_t a3, uint32_t b0, uint32_t b1) {
    asm volatile("mma.sync.aligned.m16n8k16.row.col.f32.bf16.bf16.f32 "
                 "{%0,%1,%2,%3}, {%4,%5,%6,%7}, {%8,%9}, {%0,%1,%2,%3};"
                 : "+f"(d[0]), "+f"(d[1]), "+f"(d[2]), "+f"(d[3])
                 : "r"(a0), "r"(a1), "r"(a2), "r"(a3), "r"(b0), "r"(b1));
}
__device__ __forceinline__ void ldm4(uint32_t& r0, uint32_t& r1, uint32_t& r2,
                                     uint32_t& r3, uint32_t addr) {
    asm volatile("ldmatrix.sync.aligned.m8n8.x4.shared.b16 {%0,%1,%2,%3}, [%4];"
                 : "=r"(r0), "=r"(r1), "=r"(r2), "=r"(r3) : "r"(addr));
}

// ---------------- 0a) fold spatial-attention kernels ----------------
__global__ void prep_k(const float* __restrict__ c1a, const float* __restrict__ c1b,
                       const float* __restrict__ c2a, const float* __restrict__ c2b,
                       const float* __restrict__ c3) {
    int tid = threadIdx.x;
    float w3 = c3[0], w7 = c3[1];
    for (int e = tid; e < 49*32; e += 256) {
        int t = e >> 5, i = e & 31;
        int ty = t / 7 - 3, tx = t % 7 - 3;
        float s = 0.f;
        for (int o = 0; o < 32; o++)
            s += c2b[o] * c2a[((o*32 + i)*7 + (tx+3))*7 + (ty+3)];
        s *= w7;
        if (tx >= -1 && tx <= 1 && ty >= -1 && ty <= 1) {
            float s1 = 0.f;
            for (int o = 0; o < 32; o++)
                s1 += c1b[o] * c1a[((o*32 + i)*3 + (tx+1))*3 + (ty+1)];
            s += w3 * s1;
        }
        g_kcomb[e] = s;
    }
}

// ---------------- 0b) padded bf16 weight tiles for mma convs ----------------
__global__ void prep_wb_k(const float* __restrict__ w0p, const float* __restrict__ w1p,
                          const float* __restrict__ w2p) {
    int cv = blockIdx.x, tid = threadIdx.x;
    const float* W = (cv == 0) ? w0p : ((cv == 1) ? w1p : w2p);
    __nv_bfloat16* out = g_Wb + (size_t)cv*WB_ROWS*WB_STR;
    for (int e = tid; e < WB_ROWS*WB_STR; e += 256) {
        int row = e / WB_STR, k = e % WB_STR;
        int pass = row / 96, r2 = row % 96;
        int dh = r2 / 32, o = r2 % 32;
        float v = 0.f;
        if (k < 96) {
            int dw = k >> 5, i = k & 31;
            v = W[((o*32 + i)*3 + dw)*3 + dh];   // tap-swap for (0,3,2,1) world
        }
        __nv_bfloat16 hb = __float2bfloat16(v);
        out[e] = (pass == 0) ? hb : __float2bfloat16(v - __bfloat162float(hb));
    }
}

// ---------------- 1) stats stage 1 ----------------
__global__ __launch_bounds__(256) void stats1_k(const float* __restrict__ xfu,
                                                const float* __restrict__ xhsi) {
    __shared__ float sx[256*32];
    __shared__ float sh[8][32];
    int b = blockIdx.y, blk = blockIdx.x, tid = threadIdx.x;
    size_t base = ((size_t)b*NPIX + (size_t)blk*256) * 32;
    for (int k = 0; k < 32; k++) sx[k*256 + tid] = xfu[base + (size_t)k*256 + tid];
    {
        int c = tid & 31, grp = tid >> 5;
        float s = 0.f;
        for (int p = grp; p < 256; p += 8) s += xhsi[base + (size_t)p*32 + c];
        sh[grp][c] = s;
    }
    __syncthreads();
    int e0 = tid * 4;
    int i = e0 >> 5, j0 = e0 & 31;
    float4 a = make_float4(0.f, 0.f, 0.f, 0.f);
    const float4* sx4 = (const float4*)sx;
    for (int p = 0; p < 256; p++) {
        float xi = sx[p*32 + i];
        float4 xj = sx4[p*8 + (j0 >> 2)];
        a.x += xi * xj.x; a.y += xi * xj.y; a.z += xi * xj.z; a.w += xi * xj.w;
    }
    float* part = &g_part[((size_t)b*256 + blk) * 1056];
    ((float4*)part)[tid] = a;
    if (tid < 32) {
        float t = 0.f;
        for (int g = 0; g < 8; g++) t += sh[g][tid];
        part[1024 + tid] = t;
    }
}

// ---------------- 1b) parallel reduce of partials ----------------
__global__ __launch_bounds__(256) void red_k() {
    __shared__ float sred[8][32];
    int b = blockIdx.y, e0 = blockIdx.x * 32;
    int lane = threadIdx.x & 31, gr = threadIdx.x >> 5;
    float s = 0.f;
    for (int blk = gr; blk < 256; blk += 8)
        s += g_part[((size_t)b*256 + blk)*1056 + e0 + lane];
    sred[gr][lane] = s;
    __syncthreads();
    if (threadIdx.x < 32) {
        float t = 0.f;
        #pragma unroll
        for (int g = 0; g < 8; g++) t += sred[g][lane];
        g_cov[b*1056 + e0 + lane] = t;
    }
}

// ---------------- 2) stats stage 2 ----------------
__global__ __launch_bounds__(256) void stats2_k(const float* __restrict__ Wq,
                                                const float* __restrict__ Wk,
                                                const float* __restrict__ fc1,
                                                const float* __restrict__ fc2,
                                                const float* __restrict__ projW,
                                                float* __restrict__ cm_out) {
    int b = blockIdx.x, tid = threadIdx.x;
    __shared__ float scov[1024], savg[32], sQ[1024], sK[1024];
    __shared__ float snq[32], snk[32], sG[256], sA[256], shid[32];
    for (int e = tid; e < 1024; e += 256) scov[e] = g_cov[b*1056 + e];
    if (tid < 32) savg[tid] = g_cov[b*1056 + 1024 + tid] * (1.f / (float)NPIX);
    __syncthreads();
    for (int e = tid; e < 2048; e += 256) {
        int which = e >> 10; int r = e & 1023; int c = r >> 5, i = r & 31;
        const float* Wm = which ? Wk : Wq;
        float s = 0.f;
        for (int j = 0; j < 32; j++) s += scov[i*32 + j] * Wm[c*32 + j];
        if (which) sK[c*32 + i] = s; else sQ[c*32 + i] = s;
    }
    __syncthreads();
    if (tid < 32) { float s = 0.f; for (int i = 0; i < 32; i++) s += Wq[tid*32+i]*sQ[tid*32+i]; snq[tid] = sqrtf(fmaxf(s, 0.f)); }
    else if (tid < 64) { int c = tid-32; float s = 0.f; for (int i = 0; i < 32; i++) s += Wk[c*32+i]*sK[c*32+i]; snk[c] = sqrtf(fmaxf(s, 0.f)); }
    {
        int h = tid >> 6, d = (tid >> 3) & 7, e = tid & 7;
        float s = 0.f;
        for (int i = 0; i < 32; i++) s += Wk[(h*8+d)*32 + i] * sQ[(h*8+e)*32 + i];
        sG[tid] = s;
    }
    if (tid >= 64 && tid < 96) {
        int o = tid - 64; float s = 0.f;
        for (int i = 0; i < 32; i++) s += fc1[o*32 + i] * savg[i];
        shid[o] = fmaxf(s, 0.f);
    }
    __syncthreads();
    if (tid < 32) {
        int h = tid >> 3, d = tid & 7;
        float l[8]; float mx = -1e30f;
        float nk = fmaxf(snk[h*8 + d], 1e-12f);
        for (int e = 0; e < 8; e++) {
            float nq = fmaxf(snq[h*8 + e], 1e-12f);
            l[e] = sG[h*64 + d*8 + e] / (nk * nq);
            mx = fmaxf(mx, l[e]);
        }
        float ssum = 0.f;
        for (int e = 0; e < 8; e++) { l[e] = expf(l[e] - mx); ssum += l[e]; }
        float inv = 1.f / ssum;
        for (int e = 0; e < 8; e++) sA[h*64 + d*8 + e] = l[e] * inv;
    } else if (tid >= 128 && tid < 160) {
        int c = tid - 128; float s = 0.f;
        for (int i = 0; i < 32; i++) s += fc2[c*32 + i] * shid[i];
        float m = sigmoidf_(s);
        cm_out[b*32 + c] = m;
        g_cmask[b*32 + c] = m;
    }
    __syncthreads();
    // M = projW @ blockdiag(A), written as split-bf16 padded tile [pass][o][40]
    for (int e = tid; e < 1024; e += 256) {
        int o = e >> 5, cp = e & 31, hp = cp >> 3, dp = cp & 7;
        float s = 0.f;
        for (int d = 0; d < 8; d++) s += projW[o*32 + hp*8 + d] * sA[hp*64 + d*8 + dp];
        __nv_bfloat16 hb = __float2bfloat16(s);
        g_Mbt[b*MB_ELEM + o*40 + cp] = hb;
        g_Mbt[b*MB_ELEM + 1280 + o*40 + cp] = __float2bfloat16(s - __bfloat162float(hb));
    }
}

// ---------------- 3) spatial mask: 16w x 32h tile, 256 thr, 2 px/thread ----------------
#define SM_TW 16
#define SM_TH 32
#define SM_CW 22
#define SM_CWP 23
#define SM_RH 38
#define SM_STR 36
#define SMASK_XF (SM_RH*SM_CWP*SM_STR)
#define SMASK_SMEM ((SMASK_XF + 49*32) * 4)

__global__ __launch_bounds__(256) void smask_k(const float* __restrict__ xmsi,
                                               float* __restrict__ sm_out) {
    extern __shared__ float dyn[];
    float* sx = dyn;
    float* kc = dyn + SMASK_XF;
    int tid = threadIdx.x, bx = blockIdx.x, by = blockIdx.y, b = blockIdx.z;
    for (int e = tid; e < 49*32; e += 256) kc[e] = g_kcomb[e];
    for (int slot = tid; slot < SM_RH*SM_CW; slot += 256) {
        int r = slot / SM_CW, c = slot % SM_CW;
        int gh = by*SM_TH + r - 3, gw = bx*SM_TW + c - 3;
        float4* dst = (float4*)&sx[(r*SM_CWP + c)*SM_STR];
        if ((unsigned)gh < (unsigned)HH && (unsigned)gw < (unsigned)WW) {
            const float4* src = (const float4*)(xmsi + (((size_t)b*HH + gh)*WW + gw)*32);
            #pragma unroll
            for (int i4 = 0; i4 < 8; i4++) dst[i4] = src[i4];
        } else {
            #pragma unroll
            for (int i4 = 0; i4 < 8; i4++) dst[i4] = make_float4(0.f,0.f,0.f,0.f);
        }
    }
    __syncthreads();
    int ty = tid >> 3, tq = (tid & 7) * 2;
    ull acc[2];
    acc[0] = 0ull; acc[1] = 0ull;
    #pragma unroll 1
    for (int cg = 0; cg < 8; cg++) {
        #pragma unroll 1
        for (int dy = 0; dy < 7; dy++) {
            ulonglong2 xw[8];
            #pragma unroll
            for (int j = 0; j < 8; j++)
                xw[j] = *(const ulonglong2*)&sx[((ty+dy)*SM_CWP + tq + j)*SM_STR + cg*4];
            #pragma unroll
            for (int dx = 0; dx < 7; dx++) {
                ulonglong2 wv = *(const ulonglong2*)&kc[(dy*7 + dx)*32 + cg*4];
                fma2(acc[0], xw[dx].x,   wv.x);
                fma2(acc[0], xw[dx].y,   wv.y);
                fma2(acc[1], xw[dx+1].x, wv.x);
                fma2(acc[1], xw[dx+1].y, wv.y);
            }
        }
    }
    int h = by*SM_TH + ty;
    #pragma unroll
    for (int p = 0; p < 2; p++) {
        int w = bx*SM_TW + tq + p;
        float m = sigmoidf_(hadd2(acc[p]));
        g_smask[(size_t)b*NPIX + (size_t)h*WW + w] = m;
        sm_out[(size_t)b*NPIX + (size_t)w*HH + h] = m;
    }
}

// ---------------- 4) gated V -> split bf16 planes ----------------
__global__ __launch_bounds__(256) void vgated_k(const float* __restrict__ xfu,
                                                const float* __restrict__ Wv) {
    __shared__ float ws[32*32];  // ws[i*32+o] = Wv[o*32+i]
    __shared__ float cm[32];
    int tid = threadIdx.x, h = blockIdx.x, b = blockIdx.y;
    for (int e = tid; e < 1024; e += 256) {
        int o = e >> 5, i = e & 31;
        ws[i*32 + o] = Wv[e];
    }
    if (tid < 32) cm[tid] = g_cmask[b*32 + tid];
    __syncthreads();
    size_t pidx = (size_t)b*NPIX + (size_t)h*WW + tid;
    const float4* px = (const float4*)(xfu + pidx*32);
    ull acc[16];
    #pragma unroll
    for (int q = 0; q < 16; q++) acc[q] = 0ull;
    #pragma unroll
    for (int i4 = 0; i4 < 8; i4++) {
        float4 v = px[i4];
        #pragma unroll
        for (int i = 0; i < 4; i++) {
            ull a = pk2((&v.x)[i]);
            const ulonglong2* wr = (const ulonglong2*)&ws[(i4*4 + i)*32];
            #pragma unroll
            for (int q = 0; q < 8; q++) {
                ulonglong2 wv = wr[q];
                fma2(acc[2*q], a, wv.x);
                fma2(acc[2*q+1], a, wv.y);
            }
        }
    }
    float sm = g_smask[pidx];
    uint32_t hw[16], lw[16];
    #pragma unroll
    for (int q = 0; q < 16; q++) {
        float2 f = upk(acc[q]);
        float r0 = f.x * sm * cm[2*q], r1 = f.y * sm * cm[2*q+1];
        __nv_bfloat16 h0 = __float2bfloat16(r0), h1 = __float2bfloat16(r1);
        hw[q] = (uint32_t)__bfloat16_as_ushort(h1) << 16 | __bfloat16_as_ushort(h0);
        lw[q] = pkbf(r0 - __bfloat162float(h0), r1 - __bfloat162float(h1));
    }
    uint4* oh = (uint4*)(g_vg_hi + pidx*32);
    uint4* ol = (uint4*)(g_vg_lo + pidx*32);
    #pragma unroll
    for (int q4 = 0; q4 < 4; q4++) {
        oh[q4] = make_uint4(hw[q4*4], hw[q4*4+1], hw[q4*4+2], hw[q4*4+3]);
        ol[q4] = make_uint4(lw[q4*4], lw[q4*4+1], lw[q4*4+2], lw[q4*4+3]);
    }
}

// ---------------- 5) HMMA implicit-GEMM 3x3 conv (+ fused final matvec in mode 2) ----------------
// block = 1 output row x 128 px, 128 threads (4 warps x 2 m16 tiles)
// mode 0: vg planes -> vs planes (+x_hsi resid)
// mode 1: vs planes -> tp planes (pos1 bias + gelu)
// mode 2: tp planes -> conv(pos2) + HMMA matvec M@vspec -> g_outn
#define CM_COLS 130
#define CM_PSTR 72                          // bf16 slot: 32 hi + 32 lo + 8 pad
#define CM_XELEM (3*CM_COLS*CM_PSTR)        // 28080 bf16
#define CM_WELEM (WB_ROWS*WB_STR)           // 19968 bf16
#define CM_SMEM  (CM_XELEM*2 + CM_WELEM*2 + 256)
#define CM_SMEM2 (CM_SMEM + 128*72*2 + MB_ELEM*2)

__global__ __launch_bounds__(128) void convm_k(int mode,
                                               const float* __restrict__ resid,
                                               const float* __restrict__ bias,
                                               const float* __restrict__ bias2) {
    extern __shared__ __align__(16) unsigned char smraw[];
    __nv_bfloat16* xs = (__nv_bfloat16*)smraw;
    __nv_bfloat16* wsm = xs + CM_XELEM;
    float* sb = (float*)(wsm + CM_WELEM);
    float* spb = sb + 32;
    __nv_bfloat16* vstile = (__nv_bfloat16*)(spb + 32);
    __nv_bfloat16* msm = vstile + 128*72;
    int tid = threadIdx.x;
    int b = blockIdx.z, h = blockIdx.y, w0 = blockIdx.x * 128;
    size_t rowbase = ((size_t)b*HH + h)*WW;
    const __nv_bfloat16* inH = (mode == 0) ? g_vg_hi : ((mode == 1) ? g_vs_hi : g_tp_hi);
    const __nv_bfloat16* inL = (mode == 0) ? g_vg_lo : ((mode == 1) ? g_vs_lo : g_tp_lo);
    const __nv_bfloat16* wb = g_Wb + (size_t)mode*WB_ROWS*WB_STR;
    // weights -> smem
    {
        const uint4* gw = (const uint4*)wb;
        uint4* sw = (uint4*)wsm;
        for (int e = tid; e < CM_WELEM/8; e += 128) sw[e] = gw[e];
    }
    if (tid < 32) sb[tid] = bias ? bias[tid] : 0.f;
    else if (tid < 64 && mode == 2) spb[tid-32] = bias2[tid-32];
    // x tile: 3 halo rows x 130 cols, hi plane ch 0..31, lo plane ch 32..63
    for (int f = tid; f < 3*CM_COLS*8; f += 128) {
        int cp = f >> 3, j = f & 7;
        int r = cp / CM_COLS, c = cp - r*CM_COLS;
        int gh = h - 1 + r, gw_ = w0 - 1 + c;
        int p = j >> 2, jj = j & 3;
        uint4 v = make_uint4(0,0,0,0);
        if ((unsigned)gh < (unsigned)HH && (unsigned)gw_ < (unsigned)WW) {
            const __nv_bfloat16* src = p ? inL : inH;
            v = ((const uint4*)(src + (((size_t)b*HH + gh)*WW + gw_)*32))[jj];
        }
        *(uint4*)&xs[(r*CM_COLS + c)*CM_PSTR + p*32 + jj*8] = v;
    }
    if (mode == 2) {
        for (int f = tid; f < 128*8; f += 128) {
            int px = f >> 3, j = f & 7, p = j >> 2, jj = j & 3;
            const __nv_bfloat16* src = p ? g_vs_lo : g_vs_hi;
            uint4 v = ((const uint4*)(src + (rowbase + w0 + px)*32))[jj];
            *(uint4*)&vstile[px*72 + p*32 + jj*8] = v;
        }
        const uint4* gm = (const uint4*)(g_Mbt + (size_t)b*MB_ELEM);
        uint4* sm2 = (uint4*)msm;
        for (int e = tid; e < MB_ELEM/8; e += 128) sm2[e] = gm[e];
    }
    __syncthreads();
    uint32_t xs_u = smem_to_u32(xs);
    uint32_t ws_u = smem_to_u32(wsm);
    uint32_t vs_u = smem_to_u32(vstile);
    uint32_t ms_u = smem_to_u32(msm);
    int lane = tid & 31, warp = tid >> 5;
    int g = lane >> 2, t = lane & 3;
    // ldmatrix lane maps
    int arow = lane & 15;                 // A: row within m16
    int acol8 = ((lane >> 4) & 1) * 8;    // A: k-half
    int bro = (lane & 7);                 // B: n row within n8
    int blo = ((lane >> 4) & 1);          // B: 0=hi pass rows, 1=lo pass rows
    int bc8 = ((lane >> 3) & 1) * 8;      // B: k-half
    #pragma unroll 1
    for (int tile = 0; tile < 2; tile++) {
        int p0 = warp*32 + tile*16;
        float d0[4], d1[4], d2[4], d3[4];
        #pragma unroll
        for (int q = 0; q < 4; q++) { d0[q]=0.f; d1[q]=0.f; d2[q]=0.f; d3[q]=0.f; }
        uint32_t abase = xs_u + (uint32_t)((p0 + arow)*CM_PSTR + acol8) * 2;
        #pragma unroll 1
        for (int dh = 0; dh < 3; dh++) {
            #pragma unroll 1
            for (int kc = 0; kc < 6; kc++) {
                int dw = kc >> 1, i0 = (kc & 1) << 4;
                uint32_t aaddr = abase + (uint32_t)((dh*CM_COLS + dw)*CM_PSTR + i0) * 2;
                uint32_t ah0, ah1, ah2, ah3, al0, al1, al2, al3;
                ldm4(ah0, ah1, ah2, ah3, aaddr);
                ldm4(al0, al1, al2, al3, aaddr + 64);
                int kof0 = (dw << 5) + i0;
                #pragma unroll
                for (int nc = 0; nc < 4; nc++) {
                    uint32_t baddr = ws_u + (uint32_t)(((blo*96 + dh*32 + nc*8 + bro)*WB_STR)
                                                        + kof0 + bc8) * 2;
                    uint32_t bh0, bh1, bl0, bl1;
                    ldm4(bh0, bh1, bl0, bl1, baddr);
                    float (&dd)[4] = (nc==0) ? d0 : (nc==1) ? d1 : (nc==2) ? d2 : d3;
                    mma_bf16(dd, ah0, ah1, ah2, ah3, bh0, bh1);
                    mma_bf16(dd, al0, al1, al2, al3, bh0, bh1);
                    mma_bf16(dd, ah0, ah1, ah2, ah3, bl0, bl1);
                }
            }
        }
        // matvec accumulators (mode 2)
        float m0[4], m1[4], m2[4], m3[4];
        #pragma unroll
        for (int q = 0; q < 4; q++) { m0[q]=0.f; m1[q]=0.f; m2[q]=0.f; m3[q]=0.f; }
        if (mode == 2) {
            uint32_t vbase = vs_u + (uint32_t)((p0 + arow)*72 + acol8) * 2;
            #pragma unroll
            for (int kc = 0; kc < 2; kc++) {
                int i0 = kc << 4;
                uint32_t aaddr = vbase + (uint32_t)i0 * 2;
                uint32_t ah0, ah1, ah2, ah3, al0, al1, al2, al3;
                ldm4(ah0, ah1, ah2, ah3, aaddr);
                ldm4(al0, al1, al2, al3, aaddr + 64);
                #pragma unroll
                for (int nc = 0; nc < 4; nc++) {
                    uint32_t baddr = ms_u + (uint32_t)(((blo*32 + nc*8 + bro)*40)
                                                        + i0 + bc8) * 2;
                    uint32_t bh0, bh1, bl0, bl1;
                    ldm4(bh0, bh1, bl0, bl1, baddr);
                    float (&mm)[4] = (nc==0) ? m0 : (nc==1) ? m1 : (nc==2) ? m2 : m3;
                    mma_bf16(mm, ah0, ah1, ah2, ah3, bh0, bh1);
                    mma_bf16(mm, al0, al1, al2, al3, bh0, bh1);
                    mma_bf16(mm, ah0, ah1, ah2, ah3, bl0, bl1);
                }
            }
        }
        // epilogue: lane owns rows g, g+8; channels nc*8 + 2t, +1
        int px0 = w0 + p0 + g, px1 = px0 + 8;
        #pragma unroll
        for (int nc = 0; nc < 4; nc++) {
            const float* dd = (nc==0) ? d0 : (nc==1) ? d1 : (nc==2) ? d2 : d3;
            const float* mm = (nc==0) ? m0 : (nc==1) ? m1 : (nc==2) ? m2 : m3;
            int ch = nc*8 + 2*t;
            float v0 = dd[0], v1 = dd[1];   // row g
            float u0 = dd[2], u1 = dd[3];   // row g+8
            size_t i0e = (rowbase + px0)*32 + ch;
            size_t i1e = (rowbase + px1)*32 + ch;
            if (mode == 0) {
                float2 r0 = *(const float2*)(resid + i0e);
                float2 r1 = *(const float2*)(resid + i1e);
                v0 += r0.x; v1 += r0.y; u0 += r1.x; u1 += r1.y;
                __nv_bfloat16 h0 = __float2bfloat16(v0), h1 = __float2bfloat16(v1);
                __nv_bfloat16 k0 = __float2bfloat16(u0), k1 = __float2bfloat16(u1);
                *(uint32_t*)(g_vs_hi + i0e) = (uint32_t)__bfloat16_as_ushort(h1) << 16 | __bfloat16_as_ushort(h0);
                *(uint32_t*)(g_vs_hi + i1e) = (uint32_t)__bfloat16_as_ushort(k1) << 16 | __bfloat16_as_ushort(k0);
                *(uint32_t*)(g_vs_lo + i0e) = pkbf(v0 - __bfloat162float(h0), v1 - __bfloat162float(h1));
                *(uint32_t*)(g_vs_lo + i1e) = pkbf(u0 - __bfloat162float(k0), u1 - __bfloat162float(k1));
            } else if (mode == 1) {
                v0 = gelu_exact(v0 + sb[ch]);   v1 = gelu_exact(v1 + sb[ch+1]);
                u0 = gelu_exact(u0 + sb[ch]);   u1 = gelu_exact(u1 + sb[ch+1]);
                __nv_bfloat16 h0 = __float2bfloat16(v0), h1 = __float2bfloat16(v1);
                __nv_bfloat16 k0 = __float2bfloat16(u0), k1 = __float2bfloat16(u1);
                *(uint32_t*)(g_tp_hi + i0e) = (uint32_t)__bfloat16_as_ushort(h1) << 16 | __bfloat16_as_ushort(h0);
                *(uint32_t*)(g_tp_hi + i1e) = (uint32_t)__bfloat16_as_ushort(k1) << 16 | __bfloat16_as_ushort(k0);
                *(uint32_t*)(g_tp_lo + i0e) = pkbf(v0 - __bfloat162float(h0), v1 - __bfloat162float(h1));
                *(uint32_t*)(g_tp_lo + i1e) = pkbf(u0 - __bfloat162float(k0), u1 - __bfloat162float(k1));
            } else {
                v0 += gelu_exact(mm[0] + spb[ch])   + sb[ch];
                v1 += gelu_exact(mm[1] + spb[ch+1]) + sb[ch+1];
                u0 += gelu_exact(mm[2] + spb[ch])   + sb[ch];
                u1 += gelu_exact(mm[3] + spb[ch+1]) + sb[ch+1];
                *(float2*)(g_outn + i0e) = make_float2(v0, v1);
                *(float2*)(g_outn + i1e) = make_float2(u0, u1);
            }
        }
    }
}

// ---------------- 7) transpose NHWC -> (b,c,w,h) ----------------
__global__ void transpose_k(float* __restrict__ out0) {
    __shared__ float tile[32][33];
    int b = blockIdx.z, w = blockIdx.y, h0 = blockIdx.x * 32;
    int tx = threadIdx.x, ty = threadIdx.y;
    tile[ty][tx] = g_outn[(((size_t)b*HH + (h0 + ty))*WW + w)*32 + tx];
    __syncthreads();
    out0[(((size_t)b*CC + ty)*WW + w)*HH + h0 + tx] = tile[tx][ty];
}

// ---------------- launch ----------------
extern "C" void kernel_launch(void* const* d_in, const int* in_sizes, int n_in,
                              void* d_out, int out_size) {
    const float* x_fu   = (const float*)d_in[0];
    const float* x_msi  = (const float*)d_in[1];
    const float* x_hsi  = (const float*)d_in[2];
    const float* Wq     = (const float*)d_in[3];
    const float* Wk     = (const float*)d_in[4];
    const float* Wv     = (const float*)d_in[5];
    const float* proj_W = (const float*)d_in[6];
    const float* proj_b = (const float*)d_in[7];
    const float* pos1_W = (const float*)d_in[8];
    const float* pos1_b = (const float*)d_in[9];
    const float* pos2_W = (const float*)d_in[10];
    const float* pos2_b = (const float*)d_in[11];
    const float* ca_fc1 = (const float*)d_in[12];
    const float* ca_fc2 = (const float*)d_in[13];
    const float* sa_c1a = (const float*)d_in[14];
    const float* sa_c1b = (const float*)d_in[15];
    const float* sa_c2a = (const float*)d_in[16];
    const float* sa_c2b = (const float*)d_in[17];
    const float* sa_c3  = (const float*)d_in[18];
    const float* attn_W = (const float*)d_in[19];

    float* out0   = (float*)d_out;
    float* cm_out = out0 + IMG_ELEMS;
    float* sm_out = cm_out + BB*CC;

    cudaFuncSetAttribute(smask_k, cudaFuncAttributeMaxDynamicSharedMemorySize, SMASK_SMEM);
    cudaFuncSetAttribute(convm_k, cudaFuncAttributeMaxDynamicSharedMemorySize, CM_SMEM2);

    prep_k   <<<1, 256>>>(sa_c1a, sa_c1b, sa_c2a, sa_c2b, sa_c3);
    prep_wb_k<<<3, 256>>>(attn_W, pos1_W, pos2_W);
    stats1_k <<<dim3(256, BB), 256>>>(x_fu, x_hsi);
    red_k    <<<dim3(33, BB), 256>>>();
    stats2_k <<<BB, 256>>>(Wq, Wk, ca_fc1, ca_fc2, proj_W, cm_out);
    smask_k  <<<dim3(WW/SM_TW, HH/SM_TH, BB), 256, SMASK_SMEM>>>(x_msi, sm_out);
    vgated_k <<<dim3(HH, BB), 256>>>(x_fu, Wv);

    dim3 cg(WW/128, HH, BB);
    convm_k<<<cg, 128, CM_SMEM>>>(0, x_hsi, (const float*)nullptr, (const float*)nullptr);
    convm_k<<<cg, 128, CM_SMEM>>>(1, (const float*)nullptr, pos1_b, (const float*)nullptr);
    convm_k<<<cg, 128, CM_SMEM2>>>(2, (const float*)nullptr, pos2_b, proj_b);
    transpose_k<<<dim3(HH/32, WW, BB), dim3(32, 32)>>>(out0);
}

// round 15
// speedup vs baseline: 1.0462x; 1.0462x over previous
#include <cuda_runtime.h>
#include <cuda_bf16.h>
#include <stdint.h>
#include <math.h>

// ---------------- problem constants ----------------
#define BB 4
#define HH 256
#define WW 256
#define CC 32
#define NPIX (HH*WW)            // 65536
#define IMG_ELEMS (BB*NPIX*CC)  // 8388608

typedef unsigned long long ull;

// ---------------- device scratch ----------------
__device__ float g_part[BB*256*1056];
__device__ float g_cov[BB*1056];
__device__ float g_cmask[BB*CC];
__device__ float g_smask[BB*NPIX];
__device__ float g_kcomb[49*32];
__device__ __nv_bfloat16 g_vg_hi[IMG_ELEMS], g_vg_lo[IMG_ELEMS];
__device__ __nv_bfloat16 g_vs_hi[IMG_ELEMS], g_vs_lo[IMG_ELEMS];
__device__ __nv_bfloat16 g_tp_hi[IMG_ELEMS], g_tp_lo[IMG_ELEMS];
// padded bf16 weight tiles for mma convs: [conv 3][pass 2][dh 3][o 32][k 104]
#define WB_ROWS (6*32)
#define WB_STR  104
__device__ __nv_bfloat16 g_Wb[3*WB_ROWS*WB_STR];
// per-batch split M tiles: [b][pass 2][o 32][k 40]
#define MB_ELEM 2560
__device__ __nv_bfloat16 g_Mbt[BB*MB_ELEM];

__device__ __forceinline__ float gelu_exact(float x) {
    return 0.5f * x * (1.0f + erff(x * 0.70710678118654752f));
}
__device__ __forceinline__ float sigmoidf_(float x) {
    return 1.0f / (1.0f + expf(-x));
}

// ---------------- packed f32x2 helpers ----------------
__device__ __forceinline__ void fma2(ull& c, ull a, ull b) {
    asm("fma.rn.f32x2 %0, %1, %2, %0;" : "+l"(c) : "l"(a), "l"(b));
}
__device__ __forceinline__ ull pk2(float x) {
    ull r; asm("mov.b64 %0, {%1, %1};" : "=l"(r) : "f"(x)); return r;
}
__device__ __forceinline__ float2 upk(ull v) {
    float2 f; asm("mov.b64 {%0, %1}, %2;" : "=f"(f.x), "=f"(f.y) : "l"(v)); return f;
}
__device__ __forceinline__ float hadd2(ull v) {
    float2 f = upk(v); return f.x + f.y;
}
__device__ __forceinline__ uint32_t pkbf(float a, float b) {
    __nv_bfloat16 h0 = __float2bfloat16(a), h1 = __float2bfloat16(b);
    return (uint32_t)__bfloat16_as_ushort(h1) << 16 | __bfloat16_as_ushort(h0);
}
__device__ __forceinline__ uint32_t smem_to_u32(const void* p) {
    uint32_t a; asm("{ .reg .u64 t; cvta.to.shared.u64 t, %1; cvt.u32.u64 %0, t; }" : "=r"(a) : "l"(p)); return a;
}
__device__ __forceinline__ void mma_bf16(float (&d)[4], uint32_t a0, uint32_t a1,
                                         uint32_t a2, uint32_t a3, uint32_t b0, uint32_t b1) {
    asm volatile("mma.sync.aligned.m16n8k16.row.col.f32.bf16.bf16.f32 "
                 "{%0,%1,%2,%3}, {%4,%5,%6,%7}, {%8,%9}, {%0,%1,%2,%3};"
                 : "+f"(d[0]), "+f"(d[1]), "+f"(d[2]), "+f"(d[3])
                 : "r"(a0), "r"(a1), "r"(a2), "r"(a3), "r"(b0), "r"(b1));
}
__device__ __forceinline__ void ldm4(uint32_t& r0, uint32_t& r1, uint32_t& r2,
                                     uint32_t& r3, uint32_t addr) {
    asm volatile("ldmatrix.sync.aligned.m8n8.x4.shared.b16 {%0,%1,%2,%3}, [%4];"
                 : "=r"(r0), "=r"(r1), "=r"(r2), "=r"(r3) : "r"(addr));
}

// ---------------- 0a) fold spatial-attention kernels ----------------
__global__ void prep_k(const float* __restrict__ c1a, const float* __restrict__ c1b,
                       const float* __restrict__ c2a, const float* __restrict__ c2b,
                       const float* __restrict__ c3) {
    int tid = threadIdx.x;
    float w3 = c3[0], w7 = c3[1];
    for (int e = tid; e < 49*32; e += 256) {
        int t = e >> 5, i = e & 31;
        int ty = t / 7 - 3, tx = t % 7 - 3;
        float s = 0.f;
        for (int o = 0; o < 32; o++)
            s += c2b[o] * c2a[((o*32 + i)*7 + (tx+3))*7 + (ty+3)];
        s *= w7;
        if (tx >= -1 && tx <= 1 && ty >= -1 && ty <= 1) {
            float s1 = 0.f;
            for (int o = 0; o < 32; o++)
                s1 += c1b[o] * c1a[((o*32 + i)*3 + (tx+1))*3 + (ty+1)];
            s += w3 * s1;
        }
        g_kcomb[e] = s;
    }
}

// ---------------- 0b) padded bf16 weight tiles for mma convs ----------------
// cv 0,1 (row-strip convs): stored(dh,dw) = W_ref[kh=dw, kw=dh]
// cv 2 (column-strip conv): mainloop row axis walks w -> swap dh/dw roles
__global__ void prep_wb_k(const float* __restrict__ w0p, const float* __restrict__ w1p,
                          const float* __restrict__ w2p) {
    int cv = blockIdx.x, tid = threadIdx.x;
    const float* W = (cv == 0) ? w0p : ((cv == 1) ? w1p : w2p);
    __nv_bfloat16* out = g_Wb + (size_t)cv*WB_ROWS*WB_STR;
    for (int e = tid; e < WB_ROWS*WB_STR; e += 256) {
        int row = e / WB_STR, k = e % WB_STR;
        int pass = row / 96, r2 = row % 96;
        int dh = r2 / 32, o = r2 % 32;
        float v = 0.f;
        if (k < 96) {
            int dw = k >> 5, i = k & 31;
            v = (cv == 2) ? W[((o*32 + i)*3 + dh)*3 + dw]
                          : W[((o*32 + i)*3 + dw)*3 + dh];
        }
        __nv_bfloat16 hb = __float2bfloat16(v);
        out[e] = (pass == 0) ? hb : __float2bfloat16(v - __bfloat162float(hb));
    }
}

// ---------------- 1) stats stage 1 ----------------
__global__ __launch_bounds__(256) void stats1_k(const float* __restrict__ xfu,
                                                const float* __restrict__ xhsi) {
    __shared__ float sx[256*32];
    __shared__ float sh[8][32];
    int b = blockIdx.y, blk = blockIdx.x, tid = threadIdx.x;
    size_t base = ((size_t)b*NPIX + (size_t)blk*256) * 32;
    for (int k = 0; k < 32; k++) sx[k*256 + tid] = xfu[base + (size_t)k*256 + tid];
    {
        int c = tid & 31, grp = tid >> 5;
        float s = 0.f;
        for (int p = grp; p < 256; p += 8) s += xhsi[base + (size_t)p*32 + c];
        sh[grp][c] = s;
    }
    __syncthreads();
    int e0 = tid * 4;
    int i = e0 >> 5, j0 = e0 & 31;
    float4 a = make_float4(0.f, 0.f, 0.f, 0.f);
    const float4* sx4 = (const float4*)sx;
    for (int p = 0; p < 256; p++) {
        float xi = sx[p*32 + i];
        float4 xj = sx4[p*8 + (j0 >> 2)];
        a.x += xi * xj.x; a.y += xi * xj.y; a.z += xi * xj.z; a.w += xi * xj.w;
    }
    float* part = &g_part[((size_t)b*256 + blk) * 1056];
    ((float4*)part)[tid] = a;
    if (tid < 32) {
        float t = 0.f;
        for (int g = 0; g < 8; g++) t += sh[g][tid];
        part[1024 + tid] = t;
    }
}

// ---------------- 1b) parallel reduce of partials ----------------
__global__ __launch_bounds__(256) void red_k() {
    __shared__ float sred[8][32];
    int b = blockIdx.y, e0 = blockIdx.x * 32;
    int lane = threadIdx.x & 31, gr = threadIdx.x >> 5;
    float s = 0.f;
    for (int blk = gr; blk < 256; blk += 8)
        s += g_part[((size_t)b*256 + blk)*1056 + e0 + lane];
    sred[gr][lane] = s;
    __syncthreads();
    if (threadIdx.x < 32) {
        float t = 0.f;
        #pragma unroll
        for (int g = 0; g < 8; g++) t += sred[g][lane];
        g_cov[b*1056 + e0 + lane] = t;
    }
}

// ---------------- 2) stats stage 2 ----------------
__global__ __launch_bounds__(256) void stats2_k(const float* __restrict__ Wq,
                                                const float* __restrict__ Wk,
                                                const float* __restrict__ fc1,
                                                const float* __restrict__ fc2,
                                                const float* __restrict__ projW,
                                                float* __restrict__ cm_out) {
    int b = blockIdx.x, tid = threadIdx.x;
    __shared__ float scov[1024], savg[32], sQ[1024], sK[1024];
    __shared__ float snq[32], snk[32], sG[256], sA[256], shid[32];
    for (int e = tid; e < 1024; e += 256) scov[e] = g_cov[b*1056 + e];
    if (tid < 32) savg[tid] = g_cov[b*1056 + 1024 + tid] * (1.f / (float)NPIX);
    __syncthreads();
    for (int e = tid; e < 2048; e += 256) {
        int which = e >> 10; int r = e & 1023; int c = r >> 5, i = r & 31;
        const float* Wm = which ? Wk : Wq;
        float s = 0.f;
        for (int j = 0; j < 32; j++) s += scov[i*32 + j] * Wm[c*32 + j];
        if (which) sK[c*32 + i] = s; else sQ[c*32 + i] = s;
    }
    __syncthreads();
    if (tid < 32) { float s = 0.f; for (int i = 0; i < 32; i++) s += Wq[tid*32+i]*sQ[tid*32+i]; snq[tid] = sqrtf(fmaxf(s, 0.f)); }
    else if (tid < 64) { int c = tid-32; float s = 0.f; for (int i = 0; i < 32; i++) s += Wk[c*32+i]*sK[c*32+i]; snk[c] = sqrtf(fmaxf(s, 0.f)); }
    {
        int h = tid >> 6, d = (tid >> 3) & 7, e = tid & 7;
        float s = 0.f;
        for (int i = 0; i < 32; i++) s += Wk[(h*8+d)*32 + i] * sQ[(h*8+e)*32 + i];
        sG[tid] = s;
    }
    if (tid >= 64 && tid < 96) {
        int o = tid - 64; float s = 0.f;
        for (int i = 0; i < 32; i++) s += fc1[o*32 + i] * savg[i];
        shid[o] = fmaxf(s, 0.f);
    }
    __syncthreads();
    if (tid < 32) {
        int h = tid >> 3, d = tid & 7;
        float l[8]; float mx = -1e30f;
        float nk = fmaxf(snk[h*8 + d], 1e-12f);
        for (int e = 0; e < 8; e++) {
            float nq = fmaxf(snq[h*8 + e], 1e-12f);
            l[e] = sG[h*64 + d*8 + e] / (nk * nq);
            mx = fmaxf(mx, l[e]);
        }
        float ssum = 0.f;
        for (int e = 0; e < 8; e++) { l[e] = expf(l[e] - mx); ssum += l[e]; }
        float inv = 1.f / ssum;
        for (int e = 0; e < 8; e++) sA[h*64 + d*8 + e] = l[e] * inv;
    } else if (tid >= 128 && tid < 160) {
        int c = tid - 128; float s = 0.f;
        for (int i = 0; i < 32; i++) s += fc2[c*32 + i] * shid[i];
        float m = sigmoidf_(s);
        cm_out[b*32 + c] = m;
        g_cmask[b*32 + c] = m;
    }
    __syncthreads();
    for (int e = tid; e < 1024; e += 256) {
        int o = e >> 5, cp = e & 31, hp = cp >> 3, dp = cp & 7;
        float s = 0.f;
        for (int d = 0; d < 8; d++) s += projW[o*32 + hp*8 + d] * sA[hp*64 + d*8 + dp];
        __nv_bfloat16 hb = __float2bfloat16(s);
        g_Mbt[b*MB_ELEM + o*40 + cp] = hb;
        g_Mbt[b*MB_ELEM + 1280 + o*40 + cp] = __float2bfloat16(s - __bfloat162float(hb));
    }
}

// ---------------- 3) spatial mask (R13 measured-best: 16w x 32h, 4 px/thread, 128 thr) ----------------
#define SM_TW 16
#define SM_TH 32
#define SM_CW 22
#define SM_CWP 23
#define SM_RH 38
#define SM_STR 36
#define SMASK_XF (SM_RH*SM_CWP*SM_STR)
#define SMASK_SMEM ((SMASK_XF + 49*32) * 4)

__global__ __launch_bounds__(128) void smask_k(const float* __restrict__ xmsi,
                                               float* __restrict__ sm_out) {
    extern __shared__ float dyn[];
    float* sx = dyn;
    float* kc = dyn + SMASK_XF;
    int tid = threadIdx.x, bx = blockIdx.x, by = blockIdx.y, b = blockIdx.z;
    for (int e = tid; e < 49*32; e += 128) kc[e] = g_kcomb[e];
    for (int slot = tid; slot < SM_RH*SM_CW; slot += 128) {
        int r = slot / SM_CW, c = slot % SM_CW;
        int gh = by*SM_TH + r - 3, gw = bx*SM_TW + c - 3;
        float4* dst = (float4*)&sx[(r*SM_CWP + c)*SM_STR];
        if ((unsigned)gh < (unsigned)HH && (unsigned)gw < (unsigned)WW) {
            const float4* src = (const float4*)(xmsi + (((size_t)b*HH + gh)*WW + gw)*32);
            #pragma unroll
            for (int i4 = 0; i4 < 8; i4++) dst[i4] = src[i4];
        } else {
            #pragma unroll
            for (int i4 = 0; i4 < 8; i4++) dst[i4] = make_float4(0.f,0.f,0.f,0.f);
        }
    }
    __syncthreads();
    int ty = tid >> 2, tq = (tid & 3) * 4;
    ull acc[4];
    #pragma unroll
    for (int p = 0; p < 4; p++) acc[p] = 0ull;
    #pragma unroll 1
    for (int cg = 0; cg < 8; cg++) {
        #pragma unroll 1
        for (int dy = 0; dy < 7; dy++) {
            ulonglong2 xw[10];
            #pragma unroll
            for (int j = 0; j < 10; j++)
                xw[j] = *(const ulonglong2*)&sx[((ty+dy)*SM_CWP + tq + j)*SM_STR + cg*4];
            #pragma unroll
            for (int dx = 0; dx < 7; dx++) {
                ulonglong2 wv = *(const ulonglong2*)&kc[(dy*7 + dx)*32 + cg*4];
                #pragma unroll
                for (int p = 0; p < 4; p++) {
                    fma2(acc[p], xw[dx+p].x, wv.x);
                    fma2(acc[p], xw[dx+p].y, wv.y);
                }
            }
        }
    }
    int h = by*SM_TH + ty;
    #pragma unroll
    for (int p = 0; p < 4; p++) {
        int w = bx*SM_TW + tq + p;
        float m = sigmoidf_(hadd2(acc[p]));
        g_smask[(size_t)b*NPIX + (size_t)h*WW + w] = m;
        sm_out[(size_t)b*NPIX + (size_t)w*HH + h] = m;
    }
}

// ---------------- 4) gated V -> split bf16 planes ----------------
__global__ __launch_bounds__(256) void vgated_k(const float* __restrict__ xfu,
                                                const float* __restrict__ Wv) {
    __shared__ float ws[32*32];  // ws[i*32+o] = Wv[o*32+i]
    __shared__ float cm[32];
    int tid = threadIdx.x, h = blockIdx.x, b = blockIdx.y;
    for (int e = tid; e < 1024; e += 256) {
        int o = e >> 5, i = e & 31;
        ws[i*32 + o] = Wv[e];
    }
    if (tid < 32) cm[tid] = g_cmask[b*32 + tid];
    __syncthreads();
    size_t pidx = (size_t)b*NPIX + (size_t)h*WW + tid;
    const float4* px = (const float4*)(xfu + pidx*32);
    ull acc[16];
    #pragma unroll
    for (int q = 0; q < 16; q++) acc[q] = 0ull;
    #pragma unroll
    for (int i4 = 0; i4 < 8; i4++) {
        float4 v = px[i4];
        #pragma unroll
        for (int i = 0; i < 4; i++) {
            ull a = pk2((&v.x)[i]);
            const ulonglong2* wr = (const ulonglong2*)&ws[(i4*4 + i)*32];
            #pragma unroll
            for (int q = 0; q < 8; q++) {
                ulonglong2 wv = wr[q];
                fma2(acc[2*q], a, wv.x);
                fma2(acc[2*q+1], a, wv.y);
            }
        }
    }
    float sm = g_smask[pidx];
    uint32_t hw[16], lw[16];
    #pragma unroll
    for (int q = 0; q < 16; q++) {
        float2 f = upk(acc[q]);
        float r0 = f.x * sm * cm[2*q], r1 = f.y * sm * cm[2*q+1];
        __nv_bfloat16 h0 = __float2bfloat16(r0), h1 = __float2bfloat16(r1);
        hw[q] = (uint32_t)__bfloat16_as_ushort(h1) << 16 | __bfloat16_as_ushort(h0);
        lw[q] = pkbf(r0 - __bfloat162float(h0), r1 - __bfloat162float(h1));
    }
    uint4* oh = (uint4*)(g_vg_hi + pidx*32);
    uint4* ol = (uint4*)(g_vg_lo + pidx*32);
    #pragma unroll
    for (int q4 = 0; q4 < 4; q4++) {
        oh[q4] = make_uint4(hw[q4*4], hw[q4*4+1], hw[q4*4+2], hw[q4*4+3]);
        ol[q4] = make_uint4(lw[q4*4], lw[q4*4+1], lw[q4*4+2], lw[q4*4+3]);
    }
}

// ---------------- 5) HMMA implicit-GEMM 3x3 conv ----------------
// mode 0 (row strips):    vg planes -> vs planes (+x_hsi resid)
// mode 1 (row strips):    vs planes -> tp planes (pos1 bias + gelu)
// mode 2 (COLUMN strips): tp planes -> conv(pos2) + matvec M@vspec -> out0 (b,c,w,h) DIRECT
#define CM_COLS 130
#define CM_PSTR 72                          // bf16 slot: 32 hi + 32 lo + 8 pad
#define CM_XELEM (3*CM_COLS*CM_PSTR)        // 28080 bf16
#define CM_WELEM (WB_ROWS*WB_STR)           // 19968 bf16
#define CM_SMEM  (CM_XELEM*2 + CM_WELEM*2 + 256)
#define CM_SMEM2 (CM_SMEM + 128*72*2 + MB_ELEM*2)

__global__ __launch_bounds__(128) void convm_k(int mode,
                                               const float* __restrict__ resid,
                                               const float* __restrict__ bias,
                                               const float* __restrict__ bias2,
                                               float* __restrict__ out0) {
    extern __shared__ __align__(16) unsigned char smraw[];
    __nv_bfloat16* xs = (__nv_bfloat16*)smraw;
    __nv_bfloat16* wsm = xs + CM_XELEM;
    float* sb = (float*)(wsm + CM_WELEM);
    float* spb = sb + 32;
    __nv_bfloat16* vstile = (__nv_bfloat16*)(spb + 32);
    __nv_bfloat16* msm = vstile + 128*72;
    int tid = threadIdx.x;
    int b = blockIdx.z, byfix = blockIdx.y, bx128 = blockIdx.x * 128;
    bool colmode = (mode == 2);
    const __nv_bfloat16* inH = (mode == 0) ? g_vg_hi : ((mode == 1) ? g_vs_hi : g_tp_hi);
    const __nv_bfloat16* inL = (mode == 0) ? g_vg_lo : ((mode == 1) ? g_vs_lo : g_tp_lo);
    const __nv_bfloat16* wb = g_Wb + (size_t)mode*WB_ROWS*WB_STR;
    // weights -> smem
    {
        const uint4* gw = (const uint4*)wb;
        uint4* sw = (uint4*)wsm;
        for (int e = tid; e < CM_WELEM/8; e += 128) sw[e] = gw[e];
    }
    if (tid < 32) sb[tid] = bias ? bias[tid] : 0.f;
    else if (tid < 64 && mode == 2) spb[tid-32] = bias2[tid-32];
    // x tile: 3 halo "rows" x 130 "cols" (roles of h/w swap in colmode)
    for (int f = tid; f < 3*CM_COLS*8; f += 128) {
        int cp = f >> 3, j = f & 7;
        int r = cp / CM_COLS, c = cp - r*CM_COLS;
        int gh = colmode ? (bx128 - 1 + c) : (byfix - 1 + r);
        int gw_ = colmode ? (byfix - 1 + r) : (bx128 - 1 + c);
        int p = j >> 2, jj = j & 3;
        uint4 v = make_uint4(0,0,0,0);
        if ((unsigned)gh < (unsigned)HH && (unsigned)gw_ < (unsigned)WW) {
            const __nv_bfloat16* src = p ? inL : inH;
            v = ((const uint4*)(src + (((size_t)b*HH + gh)*WW + gw_)*32))[jj];
        }
        *(uint4*)&xs[(r*CM_COLS + c)*CM_PSTR + p*32 + jj*8] = v;
    }
    if (mode == 2) {
        // vs planes for the 128 center pixels (h = bx128+px, w = byfix)
        for (int f = tid; f < 128*8; f += 128) {
            int px = f >> 3, j = f & 7, p = j >> 2, jj = j & 3;
            const __nv_bfloat16* src = p ? g_vs_lo : g_vs_hi;
            uint4 v = ((const uint4*)(src + (((size_t)b*HH + bx128 + px)*WW + byfix)*32))[jj];
            *(uint4*)&vstile[px*72 + p*32 + jj*8] = v;
        }
        const uint4* gm = (const uint4*)(g_Mbt + (size_t)b*MB_ELEM);
        uint4* sm2 = (uint4*)msm;
        for (int e = tid; e < MB_ELEM/8; e += 128) sm2[e] = gm[e];
    }
    __syncthreads();
    uint32_t xs_u = smem_to_u32(xs);
    uint32_t ws_u = smem_to_u32(wsm);
    uint32_t vs_u = smem_to_u32(vstile);
    uint32_t ms_u = smem_to_u32(msm);
    int lane = tid & 31, warp = tid >> 5;
    int g = lane >> 2, t = lane & 3;
    int arow = lane & 15;
    int acol8 = ((lane >> 4) & 1) * 8;
    int bro = (lane & 7);
    int blo = ((lane >> 4) & 1);
    int bc8 = ((lane >> 3) & 1) * 8;
    #pragma unroll 1
    for (int tile = 0; tile < 2; tile++) {
        int p0 = warp*32 + tile*16;
        float d0[4], d1[4], d2[4], d3[4];
        #pragma unroll
        for (int q = 0; q < 4; q++) { d0[q]=0.f; d1[q]=0.f; d2[q]=0.f; d3[q]=0.f; }
        uint32_t abase = xs_u + (uint32_t)((p0 + arow)*CM_PSTR + acol8) * 2;
        #pragma unroll 1
        for (int dh = 0; dh < 3; dh++) {
            #pragma unroll 1
            for (int kc = 0; kc < 6; kc++) {
                int dw = kc >> 1, i0 = (kc & 1) << 4;
                uint32_t aaddr = abase + (uint32_t)((dh*CM_COLS + dw)*CM_PSTR + i0) * 2;
                uint32_t ah0, ah1, ah2, ah3, al0, al1, al2, al3;
                ldm4(ah0, ah1, ah2, ah3, aaddr);
                ldm4(al0, al1, al2, al3, aaddr + 64);
                int kof0 = (dw << 5) + i0;
                #pragma unroll
                for (int nc = 0; nc < 4; nc++) {
                    uint32_t baddr = ws_u + (uint32_t)(((blo*96 + dh*32 + nc*8 + bro)*WB_STR)
                                                        + kof0 + bc8) * 2;
                    uint32_t bh0, bh1, bl0, bl1;
                    ldm4(bh0, bh1, bl0, bl1, baddr);
                    float (&dd)[4] = (nc==0) ? d0 : (nc==1) ? d1 : (nc==2) ? d2 : d3;
                    mma_bf16(dd, ah0, ah1, ah2, ah3, bh0, bh1);
                    mma_bf16(dd, al0, al1, al2, al3, bh0, bh1);
                    mma_bf16(dd, ah0, ah1, ah2, ah3, bl0, bl1);
                }
            }
        }
        float m0[4], m1[4], m2[4], m3[4];
        #pragma unroll
        for (int q = 0; q < 4; q++) { m0[q]=0.f; m1[q]=0.f; m2[q]=0.f; m3[q]=0.f; }
        if (mode == 2) {
            uint32_t vbase = vs_u + (uint32_t)((p0 + arow)*72 + acol8) * 2;
            #pragma unroll
            for (int kc = 0; kc < 2; kc++) {
                int i0 = kc << 4;
                uint32_t aaddr = vbase + (uint32_t)i0 * 2;
                uint32_t ah0, ah1, ah2, ah3, al0, al1, al2, al3;
                ldm4(ah0, ah1, ah2, ah3, aaddr);
                ldm4(al0, al1, al2, al3, aaddr + 64);
                #pragma unroll
                for (int nc = 0; nc < 4; nc++) {
                    uint32_t baddr = ms_u + (uint32_t)(((blo*32 + nc*8 + bro)*40)
                                                        + i0 + bc8) * 2;
                    uint32_t bh0, bh1, bl0, bl1;
                    ldm4(bh0, bh1, bl0, bl1, baddr);
                    float (&mm)[4] = (nc==0) ? m0 : (nc==1) ? m1 : (nc==2) ? m2 : m3;
                    mma_bf16(mm, ah0, ah1, ah2, ah3, bh0, bh1);
                    mma_bf16(mm, al0, al1, al2, al3, bh0, bh1);
                    mma_bf16(mm, ah0, ah1, ah2, ah3, bl0, bl1);
                }
            }
        }
        // epilogue: lane owns strip positions p0+g, p0+g+8; channels nc*8+2t, +1
        int px0 = p0 + g, px1 = px0 + 8;
        #pragma unroll
        for (int nc = 0; nc < 4; nc++) {
            const float* dd = (nc==0) ? d0 : (nc==1) ? d1 : (nc==2) ? d2 : d3;
            const float* mm = (nc==0) ? m0 : (nc==1) ? m1 : (nc==2) ? m2 : m3;
            int ch = nc*8 + 2*t;
            float v0 = dd[0], v1 = dd[1];
            float u0 = dd[2], u1 = dd[3];
            if (mode == 2) {
                // direct transposed store: out0[((b*32+c)*WW + w)*HH + h]
                int h0p = bx128 + px0, h1p = bx128 + px1;
                size_t o00 = (((size_t)b*CC + ch)*WW + byfix)*HH;
                size_t o01 = (((size_t)b*CC + ch + 1)*WW + byfix)*HH;
                out0[o00 + h0p] = v0 + gelu_exact(mm[0] + spb[ch])   + sb[ch];
                out0[o01 + h0p] = v1 + gelu_exact(mm[1] + spb[ch+1]) + sb[ch+1];
                out0[o00 + h1p] = u0 + gelu_exact(mm[2] + spb[ch])   + sb[ch];
                out0[o01 + h1p] = u1 + gelu_exact(mm[3] + spb[ch+1]) + sb[ch+1];
            } else {
                size_t rowb = ((size_t)b*HH + byfix)*WW;
                size_t i0e = (rowb + bx128 + px0)*32 + ch;
                size_t i1e = (rowb + bx128 + px1)*32 + ch;
                if (mode == 0) {
                    float2 r0 = *(const float2*)(resid + i0e);
                    float2 r1 = *(const float2*)(resid + i1e);
                    v0 += r0.x; v1 += r0.y; u0 += r1.x; u1 += r1.y;
                    __nv_bfloat16 h0 = __float2bfloat16(v0), h1 = __float2bfloat16(v1);
                    __nv_bfloat16 k0 = __float2bfloat16(u0), k1 = __float2bfloat16(u1);
                    *(uint32_t*)(g_vs_hi + i0e) = (uint32_t)__bfloat16_as_ushort(h1) << 16 | __bfloat16_as_ushort(h0);
                    *(uint32_t*)(g_vs_hi + i1e) = (uint32_t)__bfloat16_as_ushort(k1) << 16 | __bfloat16_as_ushort(k0);
                    *(uint32_t*)(g_vs_lo + i0e) = pkbf(v0 - __bfloat162float(h0), v1 - __bfloat162float(h1));
                    *(uint32_t*)(g_vs_lo + i1e) = pkbf(u0 - __bfloat162float(k0), u1 - __bfloat162float(k1));
                } else {
                    v0 = gelu_exact(v0 + sb[ch]);   v1 = gelu_exact(v1 + sb[ch+1]);
                    u0 = gelu_exact(u0 + sb[ch]);   u1 = gelu_exact(u1 + sb[ch+1]);
                    __nv_bfloat16 h0 = __float2bfloat16(v0), h1 = __float2bfloat16(v1);
                    __nv_bfloat16 k0 = __float2bfloat16(u0), k1 = __float2bfloat16(u1);
                    *(uint32_t*)(g_tp_hi + i0e) = (uint32_t)__bfloat16_as_ushort(h1) << 16 | __bfloat16_as_ushort(h0);
                    *(uint32_t*)(g_tp_hi + i1e) = (uint32_t)__bfloat16_as_ushort(k1) << 16 | __bfloat16_as_ushort(k0);
                    *(uint32_t*)(g_tp_lo + i0e) = pkbf(v0 - __bfloat162float(h0), v1 - __bfloat162float(h1));
                    *(uint32_t*)(g_tp_lo + i1e) = pkbf(u0 - __bfloat162float(k0), u1 - __bfloat162float(k1));
                }
            }
        }
    }
}

// ---------------- launch ----------------
extern "C" void kernel_launch(void* const* d_in, const int* in_sizes, int n_in,
                              void* d_out, int out_size) {
    const float* x_fu   = (const float*)d_in[0];
    const float* x_msi  = (const float*)d_in[1];
    const float* x_hsi  = (const float*)d_in[2];
    const float* Wq     = (const float*)d_in[3];
    const float* Wk     = (const float*)d_in[4];
    const float* Wv     = (const float*)d_in[5];
    const float* proj_W = (const float*)d_in[6];
    const float* proj_b = (const float*)d_in[7];
    const float* pos1_W = (const float*)d_in[8];
    const float* pos1_b = (const float*)d_in[9];
    const float* pos2_W = (const float*)d_in[10];
    const float* pos2_b = (const float*)d_in[11];
    const float* ca_fc1 = (const float*)d_in[12];
    const float* ca_fc2 = (const float*)d_in[13];
    const float* sa_c1a = (const float*)d_in[14];
    const float* sa_c1b = (const float*)d_in[15];
    const float* sa_c2a = (const float*)d_in[16];
    const float* sa_c2b = (const float*)d_in[17];
    const float* sa_c3  = (const float*)d_in[18];
    const float* attn_W = (const float*)d_in[19];

    float* out0   = (float*)d_out;
    float* cm_out = out0 + IMG_ELEMS;
    float* sm_out = cm_out + BB*CC;

    cudaFuncSetAttribute(smask_k, cudaFuncAttributeMaxDynamicSharedMemorySize, SMASK_SMEM);
    cudaFuncSetAttribute(convm_k, cudaFuncAttributeMaxDynamicSharedMemorySize, CM_SMEM2);

    prep_k   <<<1, 256>>>(sa_c1a, sa_c1b, sa_c2a, sa_c2b, sa_c3);
    prep_wb_k<<<3, 256>>>(attn_W, pos1_W, pos2_W);
    stats1_k <<<dim3(256, BB), 256>>>(x_fu, x_hsi);
    red_k    <<<dim3(33, BB), 256>>>();
    stats2_k <<<BB, 256>>>(Wq, Wk, ca_fc1, ca_fc2, proj_W, cm_out);
    smask_k  <<<dim3(WW/SM_TW, HH/SM_TH, BB), 128, SMASK_SMEM>>>(x_msi, sm_out);
    vgated_k <<<dim3(HH, BB), 256>>>(x_fu, Wv);

    dim3 cg(WW/128, HH, BB);
    convm_k<<<cg, 128, CM_SMEM>>>(0, x_hsi, (const float*)nullptr, (const float*)nullptr, (float*)nullptr);
    convm_k<<<cg, 128, CM_SMEM>>>(1, (const float*)nullptr, pos1_b, (const float*)nullptr, (float*)nullptr);
    dim3 cg2(HH/128, WW, BB);
    convm_k<<<cg2, 128, CM_SMEM2>>>(2, (const float*)nullptr, pos2_b, proj_b, out0);
}

// round 16
// speedup vs baseline: 1.1991x; 1.1462x over previous
#include <cuda_runtime.h>
#include <cuda_bf16.h>
#include <stdint.h>
#include <math.h>

// ---------------- problem constants ----------------
#define BB 4
#define HH 256
#define WW 256
#define CC 32
#define NPIX (HH*WW)            // 65536
#define IMG_ELEMS (BB*NPIX*CC)  // 8388608

typedef unsigned long long ull;

// ---------------- device scratch ----------------
__device__ float g_part[BB*256*1056];
__device__ float g_cov[BB*1056];
__device__ float g_cmask[BB*CC];
__device__ float g_smask[BB*NPIX];
__device__ float g_kcomb[49*32];
__device__ __nv_bfloat16 g_vg_hi[IMG_ELEMS], g_vg_lo[IMG_ELEMS];
__device__ __nv_bfloat16 g_vs_hi[IMG_ELEMS], g_vs_lo[IMG_ELEMS];
__device__ __nv_bfloat16 g_tp_hi[IMG_ELEMS], g_tp_lo[IMG_ELEMS];
// padded bf16 weight tiles for mma convs: [conv 3][pass 2][dh 3][o 32][k 104]
#define WB_ROWS (6*32)
#define WB_STR  104
__device__ __nv_bfloat16 g_Wb[3*WB_ROWS*WB_STR];
// per-batch split M tiles: [b][pass 2][o 32][k 40]
#define MB_ELEM 2560
__device__ __nv_bfloat16 g_Mbt[BB*MB_ELEM];

__device__ __forceinline__ float gelu_exact(float x) {
    return 0.5f * x * (1.0f + erff(x * 0.70710678118654752f));
}
__device__ __forceinline__ float sigmoidf_(float x) {
    return 1.0f / (1.0f + expf(-x));
}

// ---------------- packed f32x2 helpers ----------------
__device__ __forceinline__ void fma2(ull& c, ull a, ull b) {
    asm("fma.rn.f32x2 %0, %1, %2, %0;" : "+l"(c) : "l"(a), "l"(b));
}
__device__ __forceinline__ ull pk2(float x) {
    ull r; asm("mov.b64 %0, {%1, %1};" : "=l"(r) : "f"(x)); return r;
}
__device__ __forceinline__ float2 upk(ull v) {
    float2 f; asm("mov.b64 {%0, %1}, %2;" : "=f"(f.x), "=f"(f.y) : "l"(v)); return f;
}
__device__ __forceinline__ float hadd2(ull v) {
    float2 f = upk(v); return f.x + f.y;
}
__device__ __forceinline__ uint32_t pkbf(float a, float b) {
    __nv_bfloat16 h0 = __float2bfloat16(a), h1 = __float2bfloat16(b);
    return (uint32_t)__bfloat16_as_ushort(h1) << 16 | __bfloat16_as_ushort(h0);
}
__device__ __forceinline__ uint32_t smem_to_u32(const void* p) {
    uint32_t a; asm("{ .reg .u64 t; cvta.to.shared.u64 t, %1; cvt.u32.u64 %0, t; }" : "=r"(a) : "l"(p)); return a;
}
__device__ __forceinline__ void mma_bf16(float (&d)[4], uint32_t a0, uint32_t a1,
                                         uint32_t a2, uint32_t a3, uint32_t b0, uint32_t b1) {
    asm volatile("mma.sync.aligned.m16n8k16.row.col.f32.bf16.bf16.f32 "
                 "{%0,%1,%2,%3}, {%4,%5,%6,%7}, {%8,%9}, {%0,%1,%2,%3};"
                 : "+f"(d[0]), "+f"(d[1]), "+f"(d[2]), "+f"(d[3])
                 : "r"(a0), "r"(a1), "r"(a2), "r"(a3), "r"(b0), "r"(b1));
}
__device__ __forceinline__ void ldm4(uint32_t& r0, uint32_t& r1, uint32_t& r2,
                                     uint32_t& r3, uint32_t addr) {
    asm volatile("ldmatrix.sync.aligned.m8n8.x4.shared.b16 {%0,%1,%2,%3}, [%4];"
                 : "=r"(r0), "=r"(r1), "=r"(r2), "=r"(r3) : "r"(addr));
}

// ---------------- 0a) fold spatial-attention kernels ----------------
__global__ void prep_k(const float* __restrict__ c1a, const float* __restrict__ c1b,
                       const float* __restrict__ c2a, const float* __restrict__ c2b,
                       const float* __restrict__ c3) {
    int tid = threadIdx.x;
    float w3 = c3[0], w7 = c3[1];
    for (int e = tid; e < 49*32; e += 256) {
        int t = e >> 5, i = e & 31;
        int ty = t / 7 - 3, tx = t % 7 - 3;
        float s = 0.f;
        for (int o = 0; o < 32; o++)
            s += c2b[o] * c2a[((o*32 + i)*7 + (tx+3))*7 + (ty+3)];
        s *= w7;
        if (tx >= -1 && tx <= 1 && ty >= -1 && ty <= 1) {
            float s1 = 0.f;
            for (int o = 0; o < 32; o++)
                s1 += c1b[o] * c1a[((o*32 + i)*3 + (tx+1))*3 + (ty+1)];
            s += w3 * s1;
        }
        g_kcomb[e] = s;
    }
}

// ---------------- 0b) padded bf16 weight tiles for mma convs ----------------
__global__ void prep_wb_k(const float* __restrict__ w0p, const float* __restrict__ w1p,
                          const float* __restrict__ w2p) {
    int cv = blockIdx.x, tid = threadIdx.x;
    const float* W = (cv == 0) ? w0p : ((cv == 1) ? w1p : w2p);
    __nv_bfloat16* out = g_Wb + (size_t)cv*WB_ROWS*WB_STR;
    for (int e = tid; e < WB_ROWS*WB_STR; e += 256) {
        int row = e / WB_STR, k = e % WB_STR;
        int pass = row / 96, r2 = row % 96;
        int dh = r2 / 32, o = r2 % 32;
        float v = 0.f;
        if (k < 96) {
            int dw = k >> 5, i = k & 31;
            v = (cv == 2) ? W[((o*32 + i)*3 + dh)*3 + dw]
                          : W[((o*32 + i)*3 + dw)*3 + dh];
        }
        __nv_bfloat16 hb = __float2bfloat16(v);
        out[e] = (pass == 0) ? hb : __float2bfloat16(v - __bfloat162float(hb));
    }
}

// ---------------- 1) stats stage 1 ----------------
__global__ __launch_bounds__(256) void stats1_k(const float* __restrict__ xfu,
                                                const float* __restrict__ xhsi) {
    __shared__ float sx[256*32];
    __shared__ float sh[8][32];
    int b = blockIdx.y, blk = blockIdx.x, tid = threadIdx.x;
    size_t base = ((size_t)b*NPIX + (size_t)blk*256) * 32;
    for (int k = 0; k < 32; k++) sx[k*256 + tid] = xfu[base + (size_t)k*256 + tid];
    {
        int c = tid & 31, grp = tid >> 5;
        float s = 0.f;
        for (int p = grp; p < 256; p += 8) s += xhsi[base + (size_t)p*32 + c];
        sh[grp][c] = s;
    }
    __syncthreads();
    int e0 = tid * 4;
    int i = e0 >> 5, j0 = e0 & 31;
    float4 a = make_float4(0.f, 0.f, 0.f, 0.f);
    const float4* sx4 = (const float4*)sx;
    for (int p = 0; p < 256; p++) {
        float xi = sx[p*32 + i];
        float4 xj = sx4[p*8 + (j0 >> 2)];
        a.x += xi * xj.x; a.y += xi * xj.y; a.z += xi * xj.z; a.w += xi * xj.w;
    }
    float* part = &g_part[((size_t)b*256 + blk) * 1056];
    ((float4*)part)[tid] = a;
    if (tid < 32) {
        float t = 0.f;
        for (int g = 0; g < 8; g++) t += sh[g][tid];
        part[1024 + tid] = t;
    }
}

// ---------------- 1b) parallel reduce of partials ----------------
__global__ __launch_bounds__(256) void red_k() {
    __shared__ float sred[8][32];
    int b = blockIdx.y, e0 = blockIdx.x * 32;
    int lane = threadIdx.x & 31, gr = threadIdx.x >> 5;
    float s = 0.f;
    for (int blk = gr; blk < 256; blk += 8)
        s += g_part[((size_t)b*256 + blk)*1056 + e0 + lane];
    sred[gr][lane] = s;
    __syncthreads();
    if (threadIdx.x < 32) {
        float t = 0.f;
        #pragma unroll
        for (int g = 0; g < 8; g++) t += sred[g][lane];
        g_cov[b*1056 + e0 + lane] = t;
    }
}

// ---------------- 2) stats stage 2 ----------------
__global__ __launch_bounds__(256) void stats2_k(const float* __restrict__ Wq,
                                                const float* __restrict__ Wk,
                                                const float* __restrict__ fc1,
                                                const float* __restrict__ fc2,
                                                const float* __restrict__ projW,
                                                float* __restrict__ cm_out) {
    int b = blockIdx.x, tid = threadIdx.x;
    __shared__ float scov[1024], savg[32], sQ[1024], sK[1024];
    __shared__ float snq[32], snk[32], sG[256], sA[256], shid[32];
    for (int e = tid; e < 1024; e += 256) scov[e] = g_cov[b*1056 + e];
    if (tid < 32) savg[tid] = g_cov[b*1056 + 1024 + tid] * (1.f / (float)NPIX);
    __syncthreads();
    for (int e = tid; e < 2048; e += 256) {
        int which = e >> 10; int r = e & 1023; int c = r >> 5, i = r & 31;
        const float* Wm = which ? Wk : Wq;
        float s = 0.f;
        for (int j = 0; j < 32; j++) s += scov[i*32 + j] * Wm[c*32 + j];
        if (which) sK[c*32 + i] = s; else sQ[c*32 + i] = s;
    }
    __syncthreads();
    if (tid < 32) { float s = 0.f; for (int i = 0; i < 32; i++) s += Wq[tid*32+i]*sQ[tid*32+i]; snq[tid] = sqrtf(fmaxf(s, 0.f)); }
    else if (tid < 64) { int c = tid-32; float s = 0.f; for (int i = 0; i < 32; i++) s += Wk[c*32+i]*sK[c*32+i]; snk[c] = sqrtf(fmaxf(s, 0.f)); }
    {
        int h = tid >> 6, d = (tid >> 3) & 7, e = tid & 7;
        float s = 0.f;
        for (int i = 0; i < 32; i++) s += Wk[(h*8+d)*32 + i] * sQ[(h*8+e)*32 + i];
        sG[tid] = s;
    }
    if (tid >= 64 && tid < 96) {
        int o = tid - 64; float s = 0.f;
        for (int i = 0; i < 32; i++) s += fc1[o*32 + i] * savg[i];
        shid[o] = fmaxf(s, 0.f);
    }
    __syncthreads();
    if (tid < 32) {
        int h = tid >> 3, d = tid & 7;
        float l[8]; float mx = -1e30f;
        float nk = fmaxf(snk[h*8 + d], 1e-12f);
        for (int e = 0; e < 8; e++) {
            float nq = fmaxf(snq[h*8 + e], 1e-12f);
            l[e] = sG[h*64 + d*8 + e] / (nk * nq);
            mx = fmaxf(mx, l[e]);
        }
        float ssum = 0.f;
        for (int e = 0; e < 8; e++) { l[e] = expf(l[e] - mx); ssum += l[e]; }
        float inv = 1.f / ssum;
        for (int e = 0; e < 8; e++) sA[h*64 + d*8 + e] = l[e] * inv;
    } else if (tid >= 128 && tid < 160) {
        int c = tid - 128; float s = 0.f;
        for (int i = 0; i < 32; i++) s += fc2[c*32 + i] * shid[i];
        float m = sigmoidf_(s);
        cm_out[b*32 + c] = m;
        g_cmask[b*32 + c] = m;
    }
    __syncthreads();
    for (int e = tid; e < 1024; e += 256) {
        int o = e >> 5, cp = e & 31, hp = cp >> 3, dp = cp & 7;
        float s = 0.f;
        for (int d = 0; d < 8; d++) s += projW[o*32 + hp*8 + d] * sA[hp*64 + d*8 + dp];
        __nv_bfloat16 hb = __float2bfloat16(s);
        g_Mbt[b*MB_ELEM + o*40 + cp] = hb;
        g_Mbt[b*MB_ELEM + 1280 + o*40 + cp] = __float2bfloat16(s - __bfloat162float(hb));
    }
}

// ---------------- 3) spatial mask (R13 measured-best: 16w x 32h, 4 px/thread, 128 thr) ----------------
#define SM_TW 16
#define SM_TH 32
#define SM_CW 22
#define SM_CWP 23
#define SM_RH 38
#define SM_STR 36
#define SMASK_XF (SM_RH*SM_CWP*SM_STR)
#define SMASK_SMEM ((SMASK_XF + 49*32) * 4)

__global__ __launch_bounds__(128) void smask_k(const float* __restrict__ xmsi,
                                               float* __restrict__ sm_out) {
    extern __shared__ float dyn[];
    float* sx = dyn;
    float* kc = dyn + SMASK_XF;
    int tid = threadIdx.x, bx = blockIdx.x, by = blockIdx.y, b = blockIdx.z;
    for (int e = tid; e < 49*32; e += 128) kc[e] = g_kcomb[e];
    for (int slot = tid; slot < SM_RH*SM_CW; slot += 128) {
        int r = slot / SM_CW, c = slot % SM_CW;
        int gh = by*SM_TH + r - 3, gw = bx*SM_TW + c - 3;
        float4* dst = (float4*)&sx[(r*SM_CWP + c)*SM_STR];
        if ((unsigned)gh < (unsigned)HH && (unsigned)gw < (unsigned)WW) {
            const float4* src = (const float4*)(xmsi + (((size_t)b*HH + gh)*WW + gw)*32);
            #pragma unroll
            for (int i4 = 0; i4 < 8; i4++) dst[i4] = src[i4];
        } else {
            #pragma unroll
            for (int i4 = 0; i4 < 8; i4++) dst[i4] = make_float4(0.f,0.f,0.f,0.f);
        }
    }
    __syncthreads();
    int ty = tid >> 2, tq = (tid & 3) * 4;
    ull acc[4];
    #pragma unroll
    for (int p = 0; p < 4; p++) acc[p] = 0ull;
    #pragma unroll 1
    for (int cg = 0; cg < 8; cg++) {
        #pragma unroll 1
        for (int dy = 0; dy < 7; dy++) {
            ulonglong2 xw[10];
            #pragma unroll
            for (int j = 0; j < 10; j++)
                xw[j] = *(const ulonglong2*)&sx[((ty+dy)*SM_CWP + tq + j)*SM_STR + cg*4];
            #pragma unroll
            for (int dx = 0; dx < 7; dx++) {
                ulonglong2 wv = *(const ulonglong2*)&kc[(dy*7 + dx)*32 + cg*4];
                #pragma unroll
                for (int p = 0; p < 4; p++) {
                    fma2(acc[p], xw[dx+p].x, wv.x);
                    fma2(acc[p], xw[dx+p].y, wv.y);
                }
            }
        }
    }
    int h = by*SM_TH + ty;
    #pragma unroll
    for (int p = 0; p < 4; p++) {
        int w = bx*SM_TW + tq + p;
        float m = sigmoidf_(hadd2(acc[p]));
        g_smask[(size_t)b*NPIX + (size_t)h*WW + w] = m;
        sm_out[(size_t)b*NPIX + (size_t)w*HH + h] = m;
    }
}

// ---------------- 4) gated V -> split bf16 planes ----------------
__global__ __launch_bounds__(256) void vgated_k(const float* __restrict__ xfu,
                                                const float* __restrict__ Wv) {
    __shared__ float ws[32*32];  // ws[i*32+o] = Wv[o*32+i]
    __shared__ float cm[32];
    int tid = threadIdx.x, h = blockIdx.x, b = blockIdx.y;
    for (int e = tid; e < 1024; e += 256) {
        int o = e >> 5, i = e & 31;
        ws[i*32 + o] = Wv[e];
    }
    if (tid < 32) cm[tid] = g_cmask[b*32 + tid];
    __syncthreads();
    size_t pidx = (size_t)b*NPIX + (size_t)h*WW + tid;
    const float4* px = (const float4*)(xfu + pidx*32);
    ull acc[16];
    #pragma unroll
    for (int q = 0; q < 16; q++) acc[q] = 0ull;
    #pragma unroll
    for (int i4 = 0; i4 < 8; i4++) {
        float4 v = px[i4];
        #pragma unroll
        for (int i = 0; i < 4; i++) {
            ull a = pk2((&v.x)[i]);
            const ulonglong2* wr = (const ulonglong2*)&ws[(i4*4 + i)*32];
            #pragma unroll
            for (int q = 0; q < 8; q++) {
                ulonglong2 wv = wr[q];
                fma2(acc[2*q], a, wv.x);
                fma2(acc[2*q+1], a, wv.y);
            }
        }
    }
    float sm = g_smask[pidx];
    uint32_t hw[16], lw[16];
    #pragma unroll
    for (int q = 0; q < 16; q++) {
        float2 f = upk(acc[q]);
        float r0 = f.x * sm * cm[2*q], r1 = f.y * sm * cm[2*q+1];
        __nv_bfloat16 h0 = __float2bfloat16(r0), h1 = __float2bfloat16(r1);
        hw[q] = (uint32_t)__bfloat16_as_ushort(h1) << 16 | __bfloat16_as_ushort(h0);
        lw[q] = pkbf(r0 - __bfloat162float(h0), r1 - __bfloat162float(h1));
    }
    uint4* oh = (uint4*)(g_vg_hi + pidx*32);
    uint4* ol = (uint4*)(g_vg_lo + pidx*32);
    #pragma unroll
    for (int q4 = 0; q4 < 4; q4++) {
        oh[q4] = make_uint4(hw[q4*4], hw[q4*4+1], hw[q4*4+2], hw[q4*4+3]);
        ol[q4] = make_uint4(lw[q4*4], lw[q4*4+1], lw[q4*4+2], lw[q4*4+3]);
    }
}

// ---------------- 5) HMMA implicit-GEMM 3x3 conv (256 thr, 8 warps, 1 m16 tile/warp) ----------------
// mode 0 (row strips):    vg planes -> vs planes (+x_hsi resid)
// mode 1 (row strips):    vs planes -> tp planes (pos1 bias + gelu)
// mode 2 (COLUMN strips): tp planes -> conv(pos2) + matvec M@vspec -> out0 (b,c,w,h) DIRECT
#define CM_COLS 130
#define CM_PSTR 72                          // bf16 slot: 32 hi + 32 lo + 8 pad
#define CM_XELEM (3*CM_COLS*CM_PSTR)        // 28080 bf16
#define CM_WELEM (WB_ROWS*WB_STR)           // 19968 bf16
#define CM_SMEM  (CM_XELEM*2 + CM_WELEM*2 + 256)
#define CM_SMEM2 (CM_SMEM + 128*72*2 + MB_ELEM*2)

__global__ __launch_bounds__(256) void convm_k(int mode,
                                               const float* __restrict__ resid,
                                               const float* __restrict__ bias,
                                               const float* __restrict__ bias2,
                                               float* __restrict__ out0) {
    extern __shared__ __align__(16) unsigned char smraw[];
    __nv_bfloat16* xs = (__nv_bfloat16*)smraw;
    __nv_bfloat16* wsm = xs + CM_XELEM;
    float* sb = (float*)(wsm + CM_WELEM);
    float* spb = sb + 32;
    __nv_bfloat16* vstile = (__nv_bfloat16*)(spb + 32);
    __nv_bfloat16* msm = vstile + 128*72;
    int tid = threadIdx.x;
    int b = blockIdx.z, byfix = blockIdx.y, bx128 = blockIdx.x * 128;
    bool colmode = (mode == 2);
    const __nv_bfloat16* inH = (mode == 0) ? g_vg_hi : ((mode == 1) ? g_vs_hi : g_tp_hi);
    const __nv_bfloat16* inL = (mode == 0) ? g_vg_lo : ((mode == 1) ? g_vs_lo : g_tp_lo);
    const __nv_bfloat16* wb = g_Wb + (size_t)mode*WB_ROWS*WB_STR;
    // weights -> smem
    {
        const uint4* gw = (const uint4*)wb;
        uint4* sw = (uint4*)wsm;
        for (int e = tid; e < CM_WELEM/8; e += 256) sw[e] = gw[e];
    }
    if (tid < 32) sb[tid] = bias ? bias[tid] : 0.f;
    else if (tid < 64 && mode == 2) spb[tid-32] = bias2[tid-32];
    // x tile: 3 halo "rows" x 130 "cols" (roles of h/w swap in colmode)
    for (int f = tid; f < 3*CM_COLS*8; f += 256) {
        int cp = f >> 3, j = f & 7;
        int r = cp / CM_COLS, c = cp - r*CM_COLS;
        int gh = colmode ? (bx128 - 1 + c) : (byfix - 1 + r);
        int gw_ = colmode ? (byfix - 1 + r) : (bx128 - 1 + c);
        int p = j >> 2, jj = j & 3;
        uint4 v = make_uint4(0,0,0,0);
        if ((unsigned)gh < (unsigned)HH && (unsigned)gw_ < (unsigned)WW) {
            const __nv_bfloat16* src = p ? inL : inH;
            v = ((const uint4*)(src + (((size_t)b*HH + gh)*WW + gw_)*32))[jj];
        }
        *(uint4*)&xs[(r*CM_COLS + c)*CM_PSTR + p*32 + jj*8] = v;
    }
    if (mode == 2) {
        for (int f = tid; f < 128*8; f += 256) {
            int px = f >> 3, j = f & 7, p = j >> 2, jj = j & 3;
            const __nv_bfloat16* src = p ? g_vs_lo : g_vs_hi;
            uint4 v = ((const uint4*)(src + (((size_t)b*HH + bx128 + px)*WW + byfix)*32))[jj];
            *(uint4*)&vstile[px*72 + p*32 + jj*8] = v;
        }
        const uint4* gm = (const uint4*)(g_Mbt + (size_t)b*MB_ELEM);
        uint4* sm2 = (uint4*)msm;
        for (int e = tid; e < MB_ELEM/8; e += 256) sm2[e] = gm[e];
    }
    __syncthreads();
    uint32_t xs_u = smem_to_u32(xs);
    uint32_t ws_u = smem_to_u32(wsm);
    uint32_t vs_u = smem_to_u32(vstile);
    uint32_t ms_u = smem_to_u32(msm);
    int lane = tid & 31, warp = tid >> 5;
    int g = lane >> 2, t = lane & 3;
    int arow = lane & 15;
    int acol8 = ((lane >> 4) & 1) * 8;
    int bro = (lane & 7);
    int blo = ((lane >> 4) & 1);
    int bc8 = ((lane >> 3) & 1) * 8;
    int p0 = warp * 16;                  // 8 warps x 16 px = 128 px strip
    float d0[4], d1[4], d2[4], d3[4];
    #pragma unroll
    for (int q = 0; q < 4; q++) { d0[q]=0.f; d1[q]=0.f; d2[q]=0.f; d3[q]=0.f; }
    uint32_t abase = xs_u + (uint32_t)((p0 + arow)*CM_PSTR + acol8) * 2;
    #pragma unroll 1
    for (int dh = 0; dh < 3; dh++) {
        #pragma unroll 1
        for (int kc = 0; kc < 6; kc++) {
            int dw = kc >> 1, i0 = (kc & 1) << 4;
            uint32_t aaddr = abase + (uint32_t)((dh*CM_COLS + dw)*CM_PSTR + i0) * 2;
            uint32_t ah0, ah1, ah2, ah3, al0, al1, al2, al3;
            ldm4(ah0, ah1, ah2, ah3, aaddr);
            ldm4(al0, al1, al2, al3, aaddr + 64);
            int kof0 = (dw << 5) + i0;
            #pragma unroll
            for (int nc = 0; nc < 4; nc++) {
                uint32_t baddr = ws_u + (uint32_t)(((blo*96 + dh*32 + nc*8 + bro)*WB_STR)
                                                    + kof0 + bc8) * 2;
                uint32_t bh0, bh1, bl0, bl1;
                ldm4(bh0, bh1, bl0, bl1, baddr);
                float (&dd)[4] = (nc==0) ? d0 : (nc==1) ? d1 : (nc==2) ? d2 : d3;
                mma_bf16(dd, ah0, ah1, ah2, ah3, bh0, bh1);
                mma_bf16(dd, al0, al1, al2, al3, bh0, bh1);
                mma_bf16(dd, ah0, ah1, ah2, ah3, bl0, bl1);
            }
        }
    }
    float m0[4], m1[4], m2[4], m3[4];
    #pragma unroll
    for (int q = 0; q < 4; q++) { m0[q]=0.f; m1[q]=0.f; m2[q]=0.f; m3[q]=0.f; }
    if (mode == 2) {
        uint32_t vbase = vs_u + (uint32_t)((p0 + arow)*72 + acol8) * 2;
        #pragma unroll
        for (int kc = 0; kc < 2; kc++) {
            int i0 = kc << 4;
            uint32_t aaddr = vbase + (uint32_t)i0 * 2;
            uint32_t ah0, ah1, ah2, ah3, al0, al1, al2, al3;
            ldm4(ah0, ah1, ah2, ah3, aaddr);
            ldm4(al0, al1, al2, al3, aaddr + 64);
            #pragma unroll
            for (int nc = 0; nc < 4; nc++) {
                uint32_t baddr = ms_u + (uint32_t)(((blo*32 + nc*8 + bro)*40)
                                                    + i0 + bc8) * 2;
                uint32_t bh0, bh1, bl0, bl1;
                ldm4(bh0, bh1, bl0, bl1, baddr);
                float (&mm)[4] = (nc==0) ? m0 : (nc==1) ? m1 : (nc==2) ? m2 : m3;
                mma_bf16(mm, ah0, ah1, ah2, ah3, bh0, bh1);
                mma_bf16(mm, al0, al1, al2, al3, bh0, bh1);
                mma_bf16(mm, ah0, ah1, ah2, ah3, bl0, bl1);
            }
        }
    }
    // epilogue: lane owns strip positions p0+g, p0+g+8; channels nc*8+2t, +1
    int px0 = p0 + g, px1 = px0 + 8;
    #pragma unroll
    for (int nc = 0; nc < 4; nc++) {
        const float* dd = (nc==0) ? d0 : (nc==1) ? d1 : (nc==2) ? d2 : d3;
        const float* mm = (nc==0) ? m0 : (nc==1) ? m1 : (nc==2) ? m2 : m3;
        int ch = nc*8 + 2*t;
        float v0 = dd[0], v1 = dd[1];
        float u0 = dd[2], u1 = dd[3];
        if (mode == 2) {
            int h0p = bx128 + px0, h1p = bx128 + px1;
            size_t o00 = (((size_t)b*CC + ch)*WW + byfix)*HH;
            size_t o01 = (((size_t)b*CC + ch + 1)*WW + byfix)*HH;
            out0[o00 + h0p] = v0 + gelu_exact(mm[0] + spb[ch])   + sb[ch];
            out0[o01 + h0p] = v1 + gelu_exact(mm[1] + spb[ch+1]) + sb[ch+1];
            out0[o00 + h1p] = u0 + gelu_exact(mm[2] + spb[ch])   + sb[ch];
            out0[o01 + h1p] = u1 + gelu_exact(mm[3] + spb[ch+1]) + sb[ch+1];
        } else {
            size_t rowb = ((size_t)b*HH + byfix)*WW;
            size_t i0e = (rowb + bx128 + px0)*32 + ch;
            size_t i1e = (rowb + bx128 + px1)*32 + ch;
            if (mode == 0) {
                float2 r0 = *(const float2*)(resid + i0e);
                float2 r1 = *(const float2*)(resid + i1e);
                v0 += r0.x; v1 += r0.y; u0 += r1.x; u1 += r1.y;
                __nv_bfloat16 h0 = __float2bfloat16(v0), h1 = __float2bfloat16(v1);
                __nv_bfloat16 k0 = __float2bfloat16(u0), k1 = __float2bfloat16(u1);
                *(uint32_t*)(g_vs_hi + i0e) = (uint32_t)__bfloat16_as_ushort(h1) << 16 | __bfloat16_as_ushort(h0);
                *(uint32_t*)(g_vs_hi + i1e) = (uint32_t)__bfloat16_as_ushort(k1) << 16 | __bfloat16_as_ushort(k0);
                *(uint32_t*)(g_vs_lo + i0e) = pkbf(v0 - __bfloat162float(h0), v1 - __bfloat162float(h1));
                *(uint32_t*)(g_vs_lo + i1e) = pkbf(u0 - __bfloat162float(k0), u1 - __bfloat162float(k1));
            } else {
                v0 = gelu_exact(v0 + sb[ch]);   v1 = gelu_exact(v1 + sb[ch+1]);
                u0 = gelu_exact(u0 + sb[ch]);   u1 = gelu_exact(u1 + sb[ch+1]);
                __nv_bfloat16 h0 = __float2bfloat16(v0), h1 = __float2bfloat16(v1);
                __nv_bfloat16 k0 = __float2bfloat16(u0), k1 = __float2bfloat16(u1);
                *(uint32_t*)(g_tp_hi + i0e) = (uint32_t)__bfloat16_as_ushort(h1) << 16 | __bfloat16_as_ushort(h0);
                *(uint32_t*)(g_tp_hi + i1e) = (uint32_t)__bfloat16_as_ushort(k1) << 16 | __bfloat16_as_ushort(k0);
                *(uint32_t*)(g_tp_lo + i0e) = pkbf(v0 - __bfloat162float(h0), v1 - __bfloat162float(h1));
                *(uint32_t*)(g_tp_lo + i1e) = pkbf(u0 - __bfloat162float(k0), u1 - __bfloat162float(k1));
            }
        }
    }
}

// ---------------- launch ----------------
extern "C" void kernel_launch(void* const* d_in, const int* in_sizes, int n_in,
                              void* d_out, int out_size) {
    const float* x_fu   = (const float*)d_in[0];
    const float* x_msi  = (const float*)d_in[1];
    const float* x_hsi  = (const float*)d_in[2];
    const float* Wq     = (const float*)d_in[3];
    const float* Wk     = (const float*)d_in[4];
    const float* Wv     = (const float*)d_in[5];
    const float* proj_W = (const float*)d_in[6];
    const float* proj_b = (const float*)d_in[7];
    const float* pos1_W = (const float*)d_in[8];
    const float* pos1_b = (const float*)d_in[9];
    const float* pos2_W = (const float*)d_in[10];
    const float* pos2_b = (const float*)d_in[11];
    const float* ca_fc1 = (const float*)d_in[12];
    const float* ca_fc2 = (const float*)d_in[13];
    const float* sa_c1a = (const float*)d_in[14];
    const float* sa_c1b = (const float*)d_in[15];
    const float* sa_c2a = (const float*)d_in[16];
    const float* sa_c2b = (const float*)d_in[17];
    const float* sa_c3  = (const float*)d_in[18];
    const float* attn_W = (const float*)d_in[19];

    float* out0   = (float*)d_out;
    float* cm_out = out0 + IMG_ELEMS;
    float* sm_out = cm_out + BB*CC;

    cudaFuncSetAttribute(smask_k, cudaFuncAttributeMaxDynamicSharedMemorySize, SMASK_SMEM);
    cudaFuncSetAttribute(convm_k, cudaFuncAttributeMaxDynamicSharedMemorySize, CM_SMEM2);

    prep_k   <<<1, 256>>>(sa_c1a, sa_c1b, sa_c2a, sa_c2b, sa_c3);
    prep_wb_k<<<3, 256>>>(attn_W, pos1_W, pos2_W);
    stats1_k <<<dim3(256, BB), 256>>>(x_fu, x_hsi);
    red_k    <<<dim3(33, BB), 256>>>();
    stats2_k <<<BB, 256>>>(Wq, Wk, ca_fc1, ca_fc2, proj_W, cm_out);
    smask_k  <<<dim3(WW/SM_TW, HH/SM_TH, BB), 128, SMASK_SMEM>>>(x_msi, sm_out);
    vgated_k <<<dim3(HH, BB), 256>>>(x_fu, Wv);

    dim3 cg(WW/128, HH, BB);
    convm_k<<<cg, 256, CM_SMEM>>>(0, x_hsi, (const float*)nullptr, (const float*)nullptr, (float*)nullptr);
    convm_k<<<cg, 256, CM_SMEM>>>(1, (const float*)nullptr, pos1_b, (const float*)nullptr, (float*)nullptr);
    dim3 cg2(HH/128, WW, BB);
    convm_k<<<cg2, 256, CM_SMEM2>>>(2, (const float*)nullptr, pos2_b, proj_b, out0);
}